// round 3
// baseline (speedup 1.0000x reference)
#include <cuda_runtime.h>
#include <cuda_bf16.h>
#include <cstdint>

#define N_CAP 100000
#define E_CAP 1600000

// ---------------- scratch (__device__ globals: no allocation in kernel_launch) ----
__device__ float g_dinv[2][N_CAP];
__device__ int   g_deg[2][N_CAP];
__device__ int   g_incl[2][N_CAP];
__device__ int   g_rowptr[2][N_CAP + 1];
__device__ int   g_cursor[2][N_CAP];
__device__ int   g_bsum[2][128];
__device__ int   g_esrc[2][E_CAP];
__device__ float g_ecoef[2][E_CAP];
__device__ float g_A[2][(size_t)N_CAP * 64];   // transformed features h (GEMM out)
__device__ float g_B[2][(size_t)N_CAP * 64];   // aggregated layer output Z

static __device__ __forceinline__ int clampi(int v, int lo, int hi) {
    return v < lo ? lo : (v > hi ? hi : v);
}

// ---------------- CSR build ----------------

__global__ void fill0_kernel(int g, int n) {
    int i = blockIdx.x * blockDim.x + threadIdx.x;
    if (i < n) g_deg[g][i] = 0;
}

__global__ void hist_kernel(int g, const int* __restrict__ dst, int E, int n) {
    int e = blockIdx.x * blockDim.x + threadIdx.x;
    if (e < E) atomicAdd(&g_deg[g][clampi(dst[e], 0, n - 1)], 1);
}

__global__ void dinv_kernel(int g, int n) {
    int i = blockIdx.x * blockDim.x + threadIdx.x;
    if (i < n) g_dinv[g][i] = rsqrtf((float)g_deg[g][i] + 1.0f);  // self-loop
}

// inclusive scan within 1024-elem blocks (Hillis-Steele)
__global__ void scan1_kernel(int g, int n) {
    __shared__ int sh[1024];
    int i = blockIdx.x * 1024 + threadIdx.x;
    int v = (i < n) ? g_deg[g][i] : 0;
    sh[threadIdx.x] = v;
    __syncthreads();
#pragma unroll
    for (int off = 1; off < 1024; off <<= 1) {
        int t = (threadIdx.x >= off) ? sh[threadIdx.x - off] : 0;
        __syncthreads();
        sh[threadIdx.x] += t;
        __syncthreads();
    }
    if (i < n) g_incl[g][i] = sh[threadIdx.x];
    if (threadIdx.x == 1023) g_bsum[g][blockIdx.x] = sh[1023];
}

__global__ void scan2_kernel(int g, int nb) {
    int run = 0;
    for (int b = 0; b < nb; b++) {
        int t = g_bsum[g][b];
        g_bsum[g][b] = run;
        run += t;
    }
}

__global__ void scan3_kernel(int g, int n, int E) {
    int i = blockIdx.x * blockDim.x + threadIdx.x;
    if (i < n) {
        int r = g_incl[g][i] - g_deg[g][i] + g_bsum[g][i >> 10];  // exclusive
        g_rowptr[g][i] = r;
        g_cursor[g][i] = r;
    }
    if (i == 0) g_rowptr[g][n] = E;
}

__global__ void claim_kernel(int g, const int* __restrict__ src,
                             const int* __restrict__ dst, int E, int n) {
    int e = blockIdx.x * blockDim.x + threadIdx.x;
    if (e >= E) return;
    int s = clampi(src[e], 0, n - 1);
    int d = clampi(dst[e], 0, n - 1);
    int pos = atomicAdd(&g_cursor[g][d], 1);
    g_esrc[g][pos] = s;
    g_ecoef[g][pos] = g_dinv[g][s] * g_dinv[g][d];
}

// ---------------- GEMM: g_A[g] = (relu?)X @ W, X external or g_B[g] ----------------

__global__ void gemm64_kernel(const float* __restrict__ Xext, int use_B,
                              const float* __restrict__ W, int g, int n, int relu_in) {
    __shared__ float Ws[64][64];
    __shared__ float Xs[64][65];
    const float* X = (use_B >= 0) ? (const float*)g_B[use_B] : Xext;
    float* Y = g_A[g];
    int tid = threadIdx.x;  // 256
    for (int i = tid; i < 64 * 16; i += 256)
        ((float4*)Ws)[i] = ((const float4*)W)[i];
    int row0 = blockIdx.x * 64;
    for (int i = tid; i < 64 * 16; i += 256) {
        int r = i >> 4, c = (i & 15) * 4;
        float4 v = make_float4(0.f, 0.f, 0.f, 0.f);
        if (row0 + r < n) v = *(const float4*)&X[(size_t)(row0 + r) * 64 + c];
        if (relu_in) {
            v.x = fmaxf(v.x, 0.f); v.y = fmaxf(v.y, 0.f);
            v.z = fmaxf(v.z, 0.f); v.w = fmaxf(v.w, 0.f);
        }
        Xs[r][c] = v.x; Xs[r][c + 1] = v.y; Xs[r][c + 2] = v.z; Xs[r][c + 3] = v.w;
    }
    __syncthreads();
    int tr = (tid >> 4) * 4;
    int tc = tid & 15;
    float acc[4][4] = {};
#pragma unroll
    for (int k = 0; k < 64; k++) {
        float4 w4 = ((const float4*)&Ws[k][0])[tc];
        float x0 = Xs[tr + 0][k], x1 = Xs[tr + 1][k];
        float x2 = Xs[tr + 2][k], x3 = Xs[tr + 3][k];
        acc[0][0] += x0 * w4.x; acc[0][1] += x0 * w4.y; acc[0][2] += x0 * w4.z; acc[0][3] += x0 * w4.w;
        acc[1][0] += x1 * w4.x; acc[1][1] += x1 * w4.y; acc[1][2] += x1 * w4.z; acc[1][3] += x1 * w4.w;
        acc[2][0] += x2 * w4.x; acc[2][1] += x2 * w4.y; acc[2][2] += x2 * w4.z; acc[2][3] += x2 * w4.w;
        acc[3][0] += x3 * w4.x; acc[3][1] += x3 * w4.y; acc[3][2] += x3 * w4.z; acc[3][3] += x3 * w4.w;
    }
#pragma unroll
    for (int i = 0; i < 4; i++) {
        int r = row0 + tr + i;
        if (r < n) {
            float4 v = make_float4(acc[i][0], acc[i][1], acc[i][2], acc[i][3]);
            *(float4*)&Y[(size_t)r * 64 + tc * 4] = v;
        }
    }
}

// ---------------- aggregation: g_B[g] = gather(g_A[g]) + self + bias ----------------
// one warp per node, lane owns 2 feature columns (float2)

__global__ void agg_kernel(int g, const float* __restrict__ b, int n) {
    int warp = (blockIdx.x * blockDim.x + threadIdx.x) >> 5;
    int lane = threadIdx.x & 31;
    if (warp >= n) return;
    const float* h = g_A[g];
    float* out = g_B[g];
    float di = g_dinv[g][warp];
    float s2 = di * di;
    float2 hv = *(const float2*)&h[(size_t)warp * 64 + lane * 2];
    float2 bv = *(const float2*)&b[lane * 2];
    float ax = fmaf(hv.x, s2, bv.x);
    float ay = fmaf(hv.y, s2, bv.y);
    int beg = g_rowptr[g][warp];
    int end = g_rowptr[g][warp + 1];
    for (int base = beg; base < end; base += 32) {
        int m = end - base;
        if (m > 32) m = 32;
        int sidx = 0;
        float cc = 0.f;
        if (lane < m) {
            sidx = g_esrc[g][base + lane];
            cc = g_ecoef[g][base + lane];
        }
        for (int j = 0; j < m; j++) {
            int ss = __shfl_sync(0xFFFFFFFFu, sidx, j);
            float c = __shfl_sync(0xFFFFFFFFu, cc, j);
            float2 gv = *(const float2*)&h[(size_t)ss * 64 + lane * 2];
            ax = fmaf(c, gv.x, ax);
            ay = fmaf(c, gv.y, ay);
        }
    }
    *(float2*)&out[(size_t)warp * 64 + lane * 2] = make_float2(ax, ay);
}

// ---------------- heads: 4 dot products per node, warp-per-node ----------------

__global__ void heads_kernel(const float* __restrict__ Wy, const float* __restrict__ by,
                             const float* __restrict__ Wp, const float* __restrict__ bp,
                             const float* __restrict__ Wb, const float* __restrict__ bb,
                             float* __restrict__ out, int n) {
    int warp = (blockIdx.x * blockDim.x + threadIdx.x) >> 5;
    int lane = threadIdx.x & 31;
    if (warp >= n) return;
    float2 xv = *(const float2*)&g_B[0][(size_t)warp * 64 + lane * 2];
    float2 xf = *(const float2*)&g_B[1][(size_t)warp * 64 + lane * 2];
    float2 wy = *(const float2*)&Wy[lane * 2];
    float2 wp = *(const float2*)&Wp[lane * 2];
    float2 wb = *(const float2*)&Wb[lane * 2];
    float sy = xv.x * wy.x + xv.y * wy.y;
    float sp = xv.x * wp.x + xv.y * wp.y;
    float sb = xv.x * wb.x + xv.y * wb.y;
    float sf = xf.x * wp.x + xf.y * wp.y;
#pragma unroll
    for (int o = 16; o; o >>= 1) {
        sy += __shfl_down_sync(0xFFFFFFFFu, sy, o);
        sp += __shfl_down_sync(0xFFFFFFFFu, sp, o);
        sb += __shfl_down_sync(0xFFFFFFFFu, sb, o);
        sf += __shfl_down_sync(0xFFFFFFFFu, sf, o);
    }
    if (lane == 0) {
        out[warp]                 = fmaxf(sy + by[0], 0.f);  // yi
        out[(size_t)n + warp]     = fmaxf(sp + bp[0], 0.f);  // fprob
        out[(size_t)2 * n + warp] = fmaxf(sf + bp[0], 0.f);  // fprob_f
        out[(size_t)3 * n + warp] = fmaxf(sb + bb[0], 0.f);  // treat_prob
    }
}

// ---------------- launch ----------------

extern "C" void kernel_launch(void* const* d_in, const int* in_sizes, int n_in,
                              void* d_out, int out_size) {
    const float* x   = (const float*)d_in[0];
    const int*   ei  = (const int*)d_in[1];    // int32: JAX x64 disabled downcasts int64
    const float* fx  = (const float*)d_in[2];
    const int*   fei = (const int*)d_in[3];
    const float* W1 = (const float*)d_in[4];
    const float* b1 = (const float*)d_in[5];
    const float* W2 = (const float*)d_in[6];
    const float* b2 = (const float*)d_in[7];
    const float* Wy = (const float*)d_in[8];
    const float* by = (const float*)d_in[9];
    const float* Wp = (const float*)d_in[10];
    const float* bp = (const float*)d_in[11];
    const float* Wb = (const float*)d_in[12];
    const float* bb = (const float*)d_in[13];

    int n = in_sizes[0] / 64;
    int E = in_sizes[1] / 2;
    float* out = (float*)d_out;

    const float* X[2]   = {x, fx};
    const int*   EIX[2] = {ei, fei};

    int nb_n = (n + 255) / 256;
    int nb_e = (E + 255) / 256;
    int nb_s = (n + 1023) / 1024;          // scan blocks
    int nb_g = (n + 63) / 64;              // gemm blocks
    int nb_w = (n * 32 + 255) / 256;       // warp-per-node kernels

    for (int g = 0; g < 2; g++) {
        const int* src = EIX[g];
        const int* dst = EIX[g] + E;

        // CSR build (reused by both layers)
        fill0_kernel<<<nb_n, 256>>>(g, n);
        hist_kernel<<<nb_e, 256>>>(g, dst, E, n);
        dinv_kernel<<<nb_n, 256>>>(g, n);
        scan1_kernel<<<nb_s, 1024>>>(g, n);
        scan2_kernel<<<1, 1>>>(g, nb_s);
        scan3_kernel<<<nb_n, 256>>>(g, n, E);
        claim_kernel<<<nb_e, 256>>>(g, src, dst, E, n);

        // layer 1: h = X @ W1 ; Z1 = gather(h) + self + b1
        gemm64_kernel<<<nb_g, 256>>>(X[g], -1, W1, g, n, 0);
        agg_kernel<<<nb_w, 256>>>(g, b1, n);

        // layer 2: h2 = relu(Z1) @ W2 ; Z2 = gather(h2) + self + b2
        gemm64_kernel<<<nb_g, 256>>>(nullptr, g, W2, g, n, 1);
        agg_kernel<<<nb_w, 256>>>(g, b2, n);
    }

    heads_kernel<<<nb_w, 256>>>(Wy, by, Wp, bp, Wb, bb, out, n);
}

// round 4
// speedup vs baseline: 1.1732x; 1.1732x over previous
#include <cuda_runtime.h>
#include <cuda_bf16.h>
#include <cstdint>

#define N_CAP 100000
#define E_CAP 1600000

// ---------------- scratch (__device__ globals) ----------------
__device__ float g_dinv[2][N_CAP];
__device__ int   g_deg[2][N_CAP];
__device__ int   g_incl[2][N_CAP];
__device__ int   g_rowptr[2][N_CAP + 1];
__device__ int   g_cursor[2][N_CAP];
__device__ int   g_bsum[2][128];
__device__ int2  g_epack[2][E_CAP];            // (src, coef-bits), written together
__device__ float g_A[2][(size_t)N_CAP * 64];   // transformed features h (GEMM out)
__device__ float g_B[2][(size_t)N_CAP * 64];   // aggregated layer output Z

static __device__ __forceinline__ int clampi(int v, int lo, int hi) {
    return v < lo ? lo : (v > hi ? hi : v);
}

// ---------------- CSR build (blockIdx.y = graph) ----------------

__global__ void fill0_kernel(int n) {
    int i = blockIdx.x * blockDim.x + threadIdx.x;
    if (i < n) g_deg[blockIdx.y][i] = 0;
}

__global__ void hist_kernel(const int* __restrict__ e0, const int* __restrict__ e1,
                            int E, int n) {
    int g = blockIdx.y;
    const int* dst = (g == 0 ? e0 : e1) + E;
    int e = blockIdx.x * blockDim.x + threadIdx.x;
    if (e < E) atomicAdd(&g_deg[g][clampi(dst[e], 0, n - 1)], 1);
}

// inclusive scan within 1024-elem blocks; also computes dinv from deg
__global__ void scan1_kernel(int n) {
    __shared__ int sh[1024];
    int g = blockIdx.y;
    int i = blockIdx.x * 1024 + threadIdx.x;
    int v = (i < n) ? g_deg[g][i] : 0;
    if (i < n) g_dinv[g][i] = rsqrtf((float)v + 1.0f);  // self-loop
    sh[threadIdx.x] = v;
    __syncthreads();
#pragma unroll
    for (int off = 1; off < 1024; off <<= 1) {
        int t = (threadIdx.x >= off) ? sh[threadIdx.x - off] : 0;
        __syncthreads();
        sh[threadIdx.x] += t;
        __syncthreads();
    }
    if (i < n) g_incl[g][i] = sh[threadIdx.x];
    if (threadIdx.x == 1023) g_bsum[g][blockIdx.x] = sh[1023];
}

__global__ void scan2_kernel(int nb) {
    int g = blockIdx.y;
    int run = 0;
    for (int b = 0; b < nb; b++) {
        int t = g_bsum[g][b];
        g_bsum[g][b] = run;
        run += t;
    }
}

__global__ void scan3_kernel(int n, int E) {
    int g = blockIdx.y;
    int i = blockIdx.x * blockDim.x + threadIdx.x;
    if (i < n) {
        int r = g_incl[g][i] - g_deg[g][i] + g_bsum[g][i >> 10];  // exclusive
        g_rowptr[g][i] = r;
        g_cursor[g][i] = r;
    }
    if (i == 0) g_rowptr[g][n] = E;
}

__global__ void claim_kernel(const int* __restrict__ e0, const int* __restrict__ e1,
                             int E, int n) {
    int g = blockIdx.y;
    const int* base = (g == 0 ? e0 : e1);
    int e = blockIdx.x * blockDim.x + threadIdx.x;
    if (e >= E) return;
    int s = clampi(base[e], 0, n - 1);
    int d = clampi(base[E + e], 0, n - 1);
    int pos = atomicAdd(&g_cursor[g][d], 1);
    float c = g_dinv[g][s] * g_dinv[g][d];
    g_epack[g][pos] = make_int2(s, __float_as_int(c));
}

// ---------------- GEMM: g_A[g] = (relu?)X @ W  (blockIdx.y = graph) ----------------

__global__ void gemm64_kernel(const float* __restrict__ X0, const float* __restrict__ X1,
                              int use_B, const float* __restrict__ W, int n, int relu_in) {
    __shared__ float Ws[64][64];
    __shared__ float Xs[64][65];
    int g = blockIdx.y;
    const float* X = use_B ? (const float*)g_B[g] : (g == 0 ? X0 : X1);
    float* Y = g_A[g];
    int tid = threadIdx.x;  // 256
    for (int i = tid; i < 64 * 16; i += 256)
        ((float4*)Ws)[i] = ((const float4*)W)[i];
    int row0 = blockIdx.x * 64;
    for (int i = tid; i < 64 * 16; i += 256) {
        int r = i >> 4, c = (i & 15) * 4;
        float4 v = make_float4(0.f, 0.f, 0.f, 0.f);
        if (row0 + r < n) v = *(const float4*)&X[(size_t)(row0 + r) * 64 + c];
        if (relu_in) {
            v.x = fmaxf(v.x, 0.f); v.y = fmaxf(v.y, 0.f);
            v.z = fmaxf(v.z, 0.f); v.w = fmaxf(v.w, 0.f);
        }
        Xs[r][c] = v.x; Xs[r][c + 1] = v.y; Xs[r][c + 2] = v.z; Xs[r][c + 3] = v.w;
    }
    __syncthreads();
    int tr = (tid >> 4) * 4;
    int tc = tid & 15;
    float acc[4][4] = {};
#pragma unroll
    for (int k = 0; k < 64; k++) {
        float4 w4 = ((const float4*)&Ws[k][0])[tc];
        float x0 = Xs[tr + 0][k], x1 = Xs[tr + 1][k];
        float x2 = Xs[tr + 2][k], x3 = Xs[tr + 3][k];
        acc[0][0] += x0 * w4.x; acc[0][1] += x0 * w4.y; acc[0][2] += x0 * w4.z; acc[0][3] += x0 * w4.w;
        acc[1][0] += x1 * w4.x; acc[1][1] += x1 * w4.y; acc[1][2] += x1 * w4.z; acc[1][3] += x1 * w4.w;
        acc[2][0] += x2 * w4.x; acc[2][1] += x2 * w4.y; acc[2][2] += x2 * w4.z; acc[2][3] += x2 * w4.w;
        acc[3][0] += x3 * w4.x; acc[3][1] += x3 * w4.y; acc[3][2] += x3 * w4.z; acc[3][3] += x3 * w4.w;
    }
#pragma unroll
    for (int i = 0; i < 4; i++) {
        int r = row0 + tr + i;
        if (r < n) {
            float4 v = make_float4(acc[i][0], acc[i][1], acc[i][2], acc[i][3]);
            *(float4*)&Y[(size_t)r * 64 + tc * 4] = v;
        }
    }
}

// ---------------- aggregation: g_B[g] = gather(g_A[g]) + self + bias --------------
// one warp per node, lane owns 2 feature cols; uniform edge loads, 4-deep unroll

__global__ void agg_kernel(const float* __restrict__ b, int n) {
    int g = blockIdx.y;
    int warp = (blockIdx.x * blockDim.x + threadIdx.x) >> 5;
    int lane = threadIdx.x & 31;
    if (warp >= n) return;
    const float* __restrict__ h = g_A[g];
    const int2*  __restrict__ ep = g_epack[g];
    float* __restrict__ out = g_B[g];

    float di = g_dinv[g][warp];
    float s2 = di * di;
    float2 hv = *(const float2*)&h[(size_t)warp * 64 + lane * 2];
    float2 bv = *(const float2*)&b[lane * 2];
    float ax0 = fmaf(hv.x, s2, bv.x), ay0 = fmaf(hv.y, s2, bv.y);
    float ax1 = 0.f, ay1 = 0.f;

    int j = g_rowptr[g][warp];
    int end = g_rowptr[g][warp + 1];
    int l2 = lane * 2;

    for (; j + 4 <= end; j += 4) {
        int2 e0 = ep[j], e1 = ep[j + 1], e2 = ep[j + 2], e3 = ep[j + 3];
        float2 v0 = *(const float2*)&h[(size_t)e0.x * 64 + l2];
        float2 v1 = *(const float2*)&h[(size_t)e1.x * 64 + l2];
        float2 v2 = *(const float2*)&h[(size_t)e2.x * 64 + l2];
        float2 v3 = *(const float2*)&h[(size_t)e3.x * 64 + l2];
        float c0 = __int_as_float(e0.y), c1 = __int_as_float(e1.y);
        float c2 = __int_as_float(e2.y), c3 = __int_as_float(e3.y);
        ax0 = fmaf(c0, v0.x, ax0); ay0 = fmaf(c0, v0.y, ay0);
        ax1 = fmaf(c1, v1.x, ax1); ay1 = fmaf(c1, v1.y, ay1);
        ax0 = fmaf(c2, v2.x, ax0); ay0 = fmaf(c2, v2.y, ay0);
        ax1 = fmaf(c3, v3.x, ax1); ay1 = fmaf(c3, v3.y, ay1);
    }
    for (; j < end; j++) {
        int2 e0 = ep[j];
        float c0 = __int_as_float(e0.y);
        float2 v0 = *(const float2*)&h[(size_t)e0.x * 64 + l2];
        ax0 = fmaf(c0, v0.x, ax0); ay0 = fmaf(c0, v0.y, ay0);
    }
    *(float2*)&out[(size_t)warp * 64 + l2] = make_float2(ax0 + ax1, ay0 + ay1);
}

// ---------------- heads: 4 dot products per node, warp-per-node ----------------

__global__ void heads_kernel(const float* __restrict__ Wy, const float* __restrict__ by,
                             const float* __restrict__ Wp, const float* __restrict__ bp,
                             const float* __restrict__ Wb, const float* __restrict__ bb,
                             float* __restrict__ out, int n) {
    int warp = (blockIdx.x * blockDim.x + threadIdx.x) >> 5;
    int lane = threadIdx.x & 31;
    if (warp >= n) return;
    float2 xv = *(const float2*)&g_B[0][(size_t)warp * 64 + lane * 2];
    float2 xf = *(const float2*)&g_B[1][(size_t)warp * 64 + lane * 2];
    float2 wy = *(const float2*)&Wy[lane * 2];
    float2 wp = *(const float2*)&Wp[lane * 2];
    float2 wb = *(const float2*)&Wb[lane * 2];
    float sy = xv.x * wy.x + xv.y * wy.y;
    float sp = xv.x * wp.x + xv.y * wp.y;
    float sb = xv.x * wb.x + xv.y * wb.y;
    float sf = xf.x * wp.x + xf.y * wp.y;
#pragma unroll
    for (int o = 16; o; o >>= 1) {
        sy += __shfl_down_sync(0xFFFFFFFFu, sy, o);
        sp += __shfl_down_sync(0xFFFFFFFFu, sp, o);
        sb += __shfl_down_sync(0xFFFFFFFFu, sb, o);
        sf += __shfl_down_sync(0xFFFFFFFFu, sf, o);
    }
    if (lane == 0) {
        out[warp]                 = fmaxf(sy + by[0], 0.f);  // yi
        out[(size_t)n + warp]     = fmaxf(sp + bp[0], 0.f);  // fprob
        out[(size_t)2 * n + warp] = fmaxf(sf + bp[0], 0.f);  // fprob_f
        out[(size_t)3 * n + warp] = fmaxf(sb + bb[0], 0.f);  // treat_prob
    }
}

// ---------------- launch ----------------

extern "C" void kernel_launch(void* const* d_in, const int* in_sizes, int n_in,
                              void* d_out, int out_size) {
    const float* x   = (const float*)d_in[0];
    const int*   ei  = (const int*)d_in[1];    // int32 on the wire (JAX x64 disabled)
    const float* fx  = (const float*)d_in[2];
    const int*   fei = (const int*)d_in[3];
    const float* W1 = (const float*)d_in[4];
    const float* b1 = (const float*)d_in[5];
    const float* W2 = (const float*)d_in[6];
    const float* b2 = (const float*)d_in[7];
    const float* Wy = (const float*)d_in[8];
    const float* by = (const float*)d_in[9];
    const float* Wp = (const float*)d_in[10];
    const float* bp = (const float*)d_in[11];
    const float* Wb = (const float*)d_in[12];
    const float* bb = (const float*)d_in[13];

    int n = in_sizes[0] / 64;
    int E = in_sizes[1] / 2;
    float* out = (float*)d_out;

    dim3 gn((n + 255) / 256, 2);
    dim3 ge((E + 255) / 256, 2);
    dim3 gs((n + 1023) / 1024, 2);
    dim3 g1(1, 2);
    dim3 gg((n + 63) / 64, 2);
    dim3 gw((n * 32 + 255) / 256, 2);
    int nb_w = (n * 32 + 255) / 256;
    int nb_s = (n + 1023) / 1024;

    // CSR build, both graphs concurrently (reused by both layers)
    fill0_kernel<<<gn, 256>>>(n);
    hist_kernel<<<ge, 256>>>(ei, fei, E, n);
    scan1_kernel<<<gs, 1024>>>(n);            // also computes dinv
    scan2_kernel<<<g1, 1>>>(nb_s);
    scan3_kernel<<<gn, 256>>>(n, E);
    claim_kernel<<<ge, 256>>>(ei, fei, E, n);

    // layer 1: h = X @ W1 ; Z1 = gather(h) + self + b1
    gemm64_kernel<<<gg, 256>>>(x, fx, 0, W1, n, 0);
    agg_kernel<<<gw, 256>>>(b1, n);

    // layer 2: h2 = relu(Z1) @ W2 ; Z2 = gather(h2) + self + b2
    gemm64_kernel<<<gg, 256>>>(nullptr, nullptr, 1, W2, n, 1);
    agg_kernel<<<gw, 256>>>(b2, n);

    heads_kernel<<<nb_w, 256>>>(Wy, by, Wp, bp, Wb, bb, out, n);
}

// round 5
// speedup vs baseline: 1.2930x; 1.1022x over previous
#include <cuda_runtime.h>
#include <cuda_fp16.h>
#include <cstdint>

#define N_CAP 100000
#define E_CAP 1600000

// ---------------- scratch (__device__ globals) ----------------
__device__ float  g_dinv[2][N_CAP];
__device__ int    g_deg[2][N_CAP];
__device__ int    g_incl[2][N_CAP];
__device__ int    g_rowptr[2][N_CAP + 1];
__device__ int    g_cursor[2][N_CAP];
__device__ int    g_bsum[2][128];
__device__ int2   g_epack[2][E_CAP];            // (src, coef-bits)
__device__ __half g_A[2][(size_t)N_CAP * 64];   // transformed features h (fp16)
__device__ float  g_B[2][(size_t)N_CAP * 64];   // layer-1 aggregated output Z1 (fp32)

static __device__ __forceinline__ int clampi(int v, int lo, int hi) {
    return v < lo ? lo : (v > hi ? hi : v);
}

// ---------------- CSR build (blockIdx.y = graph) ----------------

__global__ void fill0_kernel(int n) {
    int i = blockIdx.x * blockDim.x + threadIdx.x;
    if (i < n) g_deg[blockIdx.y][i] = 0;
}

__global__ void hist_kernel(const int* __restrict__ e0, const int* __restrict__ e1,
                            int E, int n) {
    int g = blockIdx.y;
    const int* dst = (g == 0 ? e0 : e1) + E;
    int e = blockIdx.x * blockDim.x + threadIdx.x;
    if (e < E) atomicAdd(&g_deg[g][clampi(dst[e], 0, n - 1)], 1);
}

// inclusive scan within 1024-elem blocks; also computes dinv from deg
__global__ void scan1_kernel(int n) {
    __shared__ int sh[1024];
    int g = blockIdx.y;
    int i = blockIdx.x * 1024 + threadIdx.x;
    int v = (i < n) ? g_deg[g][i] : 0;
    if (i < n) g_dinv[g][i] = rsqrtf((float)v + 1.0f);  // self-loop
    sh[threadIdx.x] = v;
    __syncthreads();
#pragma unroll
    for (int off = 1; off < 1024; off <<= 1) {
        int t = (threadIdx.x >= off) ? sh[threadIdx.x - off] : 0;
        __syncthreads();
        sh[threadIdx.x] += t;
        __syncthreads();
    }
    if (i < n) g_incl[g][i] = sh[threadIdx.x];
    if (threadIdx.x == 1023) g_bsum[g][blockIdx.x] = sh[1023];
}

// exclusive scan over <=128 block sums, 128 threads, blockIdx.y = graph
__global__ void scan2_kernel(int nb) {
    __shared__ int sh[128];
    int g = blockIdx.y;
    int t = threadIdx.x;
    int v = (t < nb) ? g_bsum[g][t] : 0;
    sh[t] = v;
    __syncthreads();
#pragma unroll
    for (int off = 1; off < 128; off <<= 1) {
        int u = (t >= off) ? sh[t - off] : 0;
        __syncthreads();
        sh[t] += u;
        __syncthreads();
    }
    if (t < nb) g_bsum[g][t] = sh[t] - v;  // exclusive
}

__global__ void scan3_kernel(int n, int E) {
    int g = blockIdx.y;
    int i = blockIdx.x * blockDim.x + threadIdx.x;
    if (i < n) {
        int r = g_incl[g][i] - g_deg[g][i] + g_bsum[g][i >> 10];  // exclusive
        g_rowptr[g][i] = r;
        g_cursor[g][i] = r;
    }
    if (i == 0) g_rowptr[g][n] = E;
}

__global__ void claim_kernel(const int* __restrict__ e0, const int* __restrict__ e1,
                             int E, int n) {
    int g = blockIdx.y;
    const int* base = (g == 0 ? e0 : e1);
    int e = blockIdx.x * blockDim.x + threadIdx.x;
    if (e >= E) return;
    int s = clampi(base[e], 0, n - 1);
    int d = clampi(base[E + e], 0, n - 1);
    int pos = atomicAdd(&g_cursor[g][d], 1);
    float c = g_dinv[g][s] * g_dinv[g][d];
    g_epack[g][pos] = make_int2(s, __float_as_int(c));
}

// ---------------- GEMM: g_A[g](fp16) = (relu?)X @ W  (blockIdx.y = graph) --------

__global__ void gemm64_kernel(const float* __restrict__ X0, const float* __restrict__ X1,
                              int use_B, const float* __restrict__ W, int n, int relu_in) {
    __shared__ float Ws[64][64];
    __shared__ float Xs[64][65];
    int g = blockIdx.y;
    const float* X = use_B ? (const float*)g_B[g] : (g == 0 ? X0 : X1);
    __half* Y = g_A[g];
    int tid = threadIdx.x;  // 256
    for (int i = tid; i < 64 * 16; i += 256)
        ((float4*)Ws)[i] = ((const float4*)W)[i];
    int row0 = blockIdx.x * 64;
    for (int i = tid; i < 64 * 16; i += 256) {
        int r = i >> 4, c = (i & 15) * 4;
        float4 v = make_float4(0.f, 0.f, 0.f, 0.f);
        if (row0 + r < n) v = *(const float4*)&X[(size_t)(row0 + r) * 64 + c];
        if (relu_in) {
            v.x = fmaxf(v.x, 0.f); v.y = fmaxf(v.y, 0.f);
            v.z = fmaxf(v.z, 0.f); v.w = fmaxf(v.w, 0.f);
        }
        Xs[r][c] = v.x; Xs[r][c + 1] = v.y; Xs[r][c + 2] = v.z; Xs[r][c + 3] = v.w;
    }
    __syncthreads();
    int tr = (tid >> 4) * 4;
    int tc = tid & 15;
    float acc[4][4] = {};
#pragma unroll
    for (int k = 0; k < 64; k++) {
        float4 w4 = ((const float4*)&Ws[k][0])[tc];
        float x0 = Xs[tr + 0][k], x1 = Xs[tr + 1][k];
        float x2 = Xs[tr + 2][k], x3 = Xs[tr + 3][k];
        acc[0][0] += x0 * w4.x; acc[0][1] += x0 * w4.y; acc[0][2] += x0 * w4.z; acc[0][3] += x0 * w4.w;
        acc[1][0] += x1 * w4.x; acc[1][1] += x1 * w4.y; acc[1][2] += x1 * w4.z; acc[1][3] += x1 * w4.w;
        acc[2][0] += x2 * w4.x; acc[2][1] += x2 * w4.y; acc[2][2] += x2 * w4.z; acc[2][3] += x2 * w4.w;
        acc[3][0] += x3 * w4.x; acc[3][1] += x3 * w4.y; acc[3][2] += x3 * w4.z; acc[3][3] += x3 * w4.w;
    }
#pragma unroll
    for (int i = 0; i < 4; i++) {
        int r = row0 + tr + i;
        if (r < n) {
            __half2 p0 = __floats2half2_rn(acc[i][0], acc[i][1]);
            __half2 p1 = __floats2half2_rn(acc[i][2], acc[i][3]);
            uint2 u = make_uint2(*(unsigned*)&p0, *(unsigned*)&p1);
            *(uint2*)&Y[(size_t)r * 64 + tc * 4] = u;
        }
    }
}

// ---------------- aggregation (+ fused heads on final layer) ----------------
// one warp per node, lane owns 2 feature cols (half2 gather = 1 L2 line/edge)

__global__ void agg_kernel(const float* __restrict__ b, int n,
                           const float* __restrict__ Wy, const float* __restrict__ by,
                           const float* __restrict__ Wp, const float* __restrict__ bp,
                           const float* __restrict__ Wb, const float* __restrict__ bb,
                           float* __restrict__ out) {
    int g = blockIdx.y;
    int warp = (blockIdx.x * blockDim.x + threadIdx.x) >> 5;
    int lane = threadIdx.x & 31;
    if (warp >= n) return;
    const __half2* __restrict__ h2 = (const __half2*)g_A[g];
    const int2*    __restrict__ ep = g_epack[g];

    float di = g_dinv[g][warp];
    float s2 = di * di;
    float2 hv = __half22float2(h2[(size_t)warp * 32 + lane]);
    float2 bv = *(const float2*)&b[lane * 2];
    float ax0 = fmaf(hv.x, s2, bv.x), ay0 = fmaf(hv.y, s2, bv.y);
    float ax1 = 0.f, ay1 = 0.f;

    int j = g_rowptr[g][warp];
    int end = g_rowptr[g][warp + 1];

    for (; j + 4 <= end; j += 4) {
        int2 e0 = ep[j], e1 = ep[j + 1], e2 = ep[j + 2], e3 = ep[j + 3];
        float2 v0 = __half22float2(h2[(size_t)e0.x * 32 + lane]);
        float2 v1 = __half22float2(h2[(size_t)e1.x * 32 + lane]);
        float2 v2 = __half22float2(h2[(size_t)e2.x * 32 + lane]);
        float2 v3 = __half22float2(h2[(size_t)e3.x * 32 + lane]);
        float c0 = __int_as_float(e0.y), c1 = __int_as_float(e1.y);
        float c2 = __int_as_float(e2.y), c3 = __int_as_float(e3.y);
        ax0 = fmaf(c0, v0.x, ax0); ay0 = fmaf(c0, v0.y, ay0);
        ax1 = fmaf(c1, v1.x, ax1); ay1 = fmaf(c1, v1.y, ay1);
        ax0 = fmaf(c2, v2.x, ax0); ay0 = fmaf(c2, v2.y, ay0);
        ax1 = fmaf(c3, v3.x, ax1); ay1 = fmaf(c3, v3.y, ay1);
    }
    for (; j < end; j++) {
        int2 e0 = ep[j];
        float c0 = __int_as_float(e0.y);
        float2 v0 = __half22float2(h2[(size_t)e0.x * 32 + lane]);
        ax0 = fmaf(c0, v0.x, ax0); ay0 = fmaf(c0, v0.y, ay0);
    }
    float zx = ax0 + ax1, zy = ay0 + ay1;  // Z cols (lane*2, lane*2+1)

    if (!Wy) {  // layer 1: store Z1
        *(float2*)&g_B[g][(size_t)warp * 64 + lane * 2] = make_float2(zx, zy);
        return;
    }
    // layer 2: fused heads, write d_out directly
    if (g == 0) {
        float2 wy = *(const float2*)&Wy[lane * 2];
        float2 wp = *(const float2*)&Wp[lane * 2];
        float2 wb = *(const float2*)&Wb[lane * 2];
        float sy = zx * wy.x + zy * wy.y;
        float sp = zx * wp.x + zy * wp.y;
        float sb = zx * wb.x + zy * wb.y;
#pragma unroll
        for (int o = 16; o; o >>= 1) {
            sy += __shfl_down_sync(0xFFFFFFFFu, sy, o);
            sp += __shfl_down_sync(0xFFFFFFFFu, sp, o);
            sb += __shfl_down_sync(0xFFFFFFFFu, sb, o);
        }
        if (lane == 0) {
            out[warp]                 = fmaxf(sy + by[0], 0.f);  // yi
            out[(size_t)n + warp]     = fmaxf(sp + bp[0], 0.f);  // fprob
            out[(size_t)3 * n + warp] = fmaxf(sb + bb[0], 0.f);  // treat_prob
        }
    } else {
        float2 wp = *(const float2*)&Wp[lane * 2];
        float sf = zx * wp.x + zy * wp.y;
#pragma unroll
        for (int o = 16; o; o >>= 1)
            sf += __shfl_down_sync(0xFFFFFFFFu, sf, o);
        if (lane == 0)
            out[(size_t)2 * n + warp] = fmaxf(sf + bp[0], 0.f);  // fprob_f
    }
}

// ---------------- launch ----------------

extern "C" void kernel_launch(void* const* d_in, const int* in_sizes, int n_in,
                              void* d_out, int out_size) {
    const float* x   = (const float*)d_in[0];
    const int*   ei  = (const int*)d_in[1];    // int32 on the wire (JAX x64 disabled)
    const float* fx  = (const float*)d_in[2];
    const int*   fei = (const int*)d_in[3];
    const float* W1 = (const float*)d_in[4];
    const float* b1 = (const float*)d_in[5];
    const float* W2 = (const float*)d_in[6];
    const float* b2 = (const float*)d_in[7];
    const float* Wy = (const float*)d_in[8];
    const float* by = (const float*)d_in[9];
    const float* Wp = (const float*)d_in[10];
    const float* bp = (const float*)d_in[11];
    const float* Wb = (const float*)d_in[12];
    const float* bb = (const float*)d_in[13];

    int n = in_sizes[0] / 64;
    int E = in_sizes[1] / 2;
    float* out = (float*)d_out;

    dim3 gn((n + 255) / 256, 2);
    dim3 ge((E + 255) / 256, 2);
    dim3 gs((n + 1023) / 1024, 2);
    dim3 g1(1, 2);
    dim3 gg((n + 63) / 64, 2);
    dim3 gw((n * 32 + 255) / 256, 2);
    int nb_s = (n + 1023) / 1024;

    // CSR build, both graphs concurrently (reused by both layers)
    fill0_kernel<<<gn, 256>>>(n);
    hist_kernel<<<ge, 256>>>(ei, fei, E, n);
    scan1_kernel<<<gs, 1024>>>(n);            // also computes dinv
    scan2_kernel<<<g1, 128>>>(nb_s);
    scan3_kernel<<<gn, 256>>>(n, E);
    claim_kernel<<<ge, 256>>>(ei, fei, E, n);

    // layer 1: h = X @ W1 (fp16) ; Z1 = gather(h) + self + b1 (fp32)
    gemm64_kernel<<<gg, 256>>>(x, fx, 0, W1, n, 0);
    agg_kernel<<<gw, 256>>>(b1, n, nullptr, nullptr, nullptr, nullptr, nullptr, nullptr, nullptr);

    // layer 2: h2 = relu(Z1) @ W2 (fp16) ; Z2 = gather + self + b2, fused heads -> out
    gemm64_kernel<<<gg, 256>>>(nullptr, nullptr, 1, W2, n, 1);
    agg_kernel<<<gw, 256>>>(b2, n, Wy, by, Wp, bp, Wb, bb, out);
}

// round 6
// speedup vs baseline: 1.3875x; 1.0731x over previous
#include <cuda_runtime.h>
#include <cuda_fp16.h>
#include <cstdint>

#define N_CAP 100000
#define E_CAP 1600000

// ---------------- scratch (__device__ globals) ----------------
__device__ float  g_dinv[2][N_CAP];
__device__ int    g_deg[2][N_CAP];
__device__ int    g_incl[2][N_CAP];
__device__ int    g_rowptr[2][N_CAP + 1];
__device__ int    g_cursor[2][N_CAP];
__device__ int    g_bsum[2][128];
__device__ int    g_esrc[2][E_CAP];             // dst-sorted src ids (coef folded into h')
__device__ __half g_A[2][(size_t)N_CAP * 64];   // h' = dinv * (X @ W), fp16
__device__ float  g_B[2][(size_t)N_CAP * 64];   // layer-1 output Z1 (fp32)

static __device__ __forceinline__ int clampi(int v, int lo, int hi) {
    return v < lo ? lo : (v > hi ? hi : v);
}

// ---------------- CSR build (blockIdx.y = graph) ----------------

__global__ void hist_kernel(const int* __restrict__ e0, const int* __restrict__ e1,
                            int E, int n) {
    int g = blockIdx.y;
    const int* dst = (g == 0 ? e0 : e1) + E;
    int e = blockIdx.x * blockDim.x + threadIdx.x;
    if (e < E) atomicAdd(&g_deg[g][clampi(dst[e], 0, n - 1)], 1);
}

// inclusive scan within 1024-elem blocks; also computes dinv from deg
__global__ void scan1_kernel(int n) {
    __shared__ int sh[1024];
    int g = blockIdx.y;
    int i = blockIdx.x * 1024 + threadIdx.x;
    int v = (i < n) ? g_deg[g][i] : 0;
    if (i < n) g_dinv[g][i] = rsqrtf((float)v + 1.0f);  // self-loop
    sh[threadIdx.x] = v;
    __syncthreads();
#pragma unroll
    for (int off = 1; off < 1024; off <<= 1) {
        int t = (threadIdx.x >= off) ? sh[threadIdx.x - off] : 0;
        __syncthreads();
        sh[threadIdx.x] += t;
        __syncthreads();
    }
    if (i < n) g_incl[g][i] = sh[threadIdx.x];
    if (threadIdx.x == 1023) g_bsum[g][blockIdx.x] = sh[1023];
}

// rowptr/cursor: per-block warp-reduce over block sums (replaces separate scan2)
__global__ void scan3_kernel(int n, int E, int nb) {
    __shared__ int sh_off;
    int g = blockIdx.y;
    int t = threadIdx.x;
    int chunk = (blockIdx.x * 256) >> 10;   // 256-node block lies in one 1024-chunk
    if (t < 32) {
        int s = 0;
        for (int k = t; k < chunk; k += 32) s += g_bsum[g][k];
#pragma unroll
        for (int o = 16; o; o >>= 1) s += __shfl_down_sync(0xFFFFFFFFu, s, o);
        if (t == 0) sh_off = s;
    }
    __syncthreads();
    int off = sh_off;
    int i = blockIdx.x * 256 + t;
    if (i < n) {
        int r = g_incl[g][i] - g_deg[g][i] + off;  // exclusive prefix
        g_rowptr[g][i] = r;
        g_cursor[g][i] = r;
    }
    if (i == 0) g_rowptr[g][n] = E;
}

// ---------------- merged: claim (CSR scatter) + layer-1 GEMM ----------------
// blocks [0, nb_e): claim; blocks [nb_e, nb_e+nb_g): gemm h' = dinv * (X @ W1)

__global__ void claimgemm_kernel(const int* __restrict__ e0, const int* __restrict__ e1,
                                 const float* __restrict__ X0, const float* __restrict__ X1,
                                 const float* __restrict__ W, int E, int n, int nb_e) {
    __shared__ float Ws[64][64];
    __shared__ float Xs[64][65];
    int g = blockIdx.y;
    int tid = threadIdx.x;

    if ((int)blockIdx.x < nb_e) {
        // ---- claim: dst-sorted edge list, src only ----
        const int* base = (g == 0 ? e0 : e1);
        int e = blockIdx.x * 256 + tid;
        if (e < E) {
            int s = clampi(base[e], 0, n - 1);
            int d = clampi(base[E + e], 0, n - 1);
            int pos = atomicAdd(&g_cursor[g][d], 1);
            g_esrc[g][pos] = s;
        }
        return;
    }

    // ---- gemm: row0 block of 64 rows ----
    const float* X = (g == 0 ? X0 : X1);
    __half* Y = g_A[g];
    for (int i = tid; i < 64 * 16; i += 256)
        ((float4*)Ws)[i] = ((const float4*)W)[i];
    int row0 = (blockIdx.x - nb_e) * 64;
    for (int i = tid; i < 64 * 16; i += 256) {
        int r = i >> 4, c = (i & 15) * 4;
        float4 v = make_float4(0.f, 0.f, 0.f, 0.f);
        if (row0 + r < n) v = *(const float4*)&X[(size_t)(row0 + r) * 64 + c];
        Xs[r][c] = v.x; Xs[r][c + 1] = v.y; Xs[r][c + 2] = v.z; Xs[r][c + 3] = v.w;
    }
    __syncthreads();
    int tr = (tid >> 4) * 4;
    int tc = tid & 15;
    float acc[4][4] = {};
#pragma unroll
    for (int k = 0; k < 64; k++) {
        float4 w4 = ((const float4*)&Ws[k][0])[tc];
        float x0 = Xs[tr + 0][k], x1 = Xs[tr + 1][k];
        float x2 = Xs[tr + 2][k], x3 = Xs[tr + 3][k];
        acc[0][0] += x0 * w4.x; acc[0][1] += x0 * w4.y; acc[0][2] += x0 * w4.z; acc[0][3] += x0 * w4.w;
        acc[1][0] += x1 * w4.x; acc[1][1] += x1 * w4.y; acc[1][2] += x1 * w4.z; acc[1][3] += x1 * w4.w;
        acc[2][0] += x2 * w4.x; acc[2][1] += x2 * w4.y; acc[2][2] += x2 * w4.z; acc[2][3] += x2 * w4.w;
        acc[3][0] += x3 * w4.x; acc[3][1] += x3 * w4.y; acc[3][2] += x3 * w4.z; acc[3][3] += x3 * w4.w;
    }
#pragma unroll
    for (int i = 0; i < 4; i++) {
        int r = row0 + tr + i;
        if (r < n) {
            float dv = g_dinv[g][r];
            __half2 p0 = __floats2half2_rn(acc[i][0] * dv, acc[i][1] * dv);
            __half2 p1 = __floats2half2_rn(acc[i][2] * dv, acc[i][3] * dv);
            uint2 u = make_uint2(*(unsigned*)&p0, *(unsigned*)&p1);
            *(uint2*)&Y[(size_t)r * 64 + tc * 4] = u;
        }
    }
}

// ---------------- layer-2 GEMM: h' = dinv * (relu(Z1) @ W2), fp16 ----------------

__global__ void gemm64_kernel(const float* __restrict__ W, int n) {
    __shared__ float Ws[64][64];
    __shared__ float Xs[64][65];
    int g = blockIdx.y;
    const float* X = g_B[g];
    __half* Y = g_A[g];
    int tid = threadIdx.x;
    for (int i = tid; i < 64 * 16; i += 256)
        ((float4*)Ws)[i] = ((const float4*)W)[i];
    int row0 = blockIdx.x * 64;
    for (int i = tid; i < 64 * 16; i += 256) {
        int r = i >> 4, c = (i & 15) * 4;
        float4 v = make_float4(0.f, 0.f, 0.f, 0.f);
        if (row0 + r < n) v = *(const float4*)&X[(size_t)(row0 + r) * 64 + c];
        v.x = fmaxf(v.x, 0.f); v.y = fmaxf(v.y, 0.f);
        v.z = fmaxf(v.z, 0.f); v.w = fmaxf(v.w, 0.f);
        Xs[r][c] = v.x; Xs[r][c + 1] = v.y; Xs[r][c + 2] = v.z; Xs[r][c + 3] = v.w;
    }
    __syncthreads();
    int tr = (tid >> 4) * 4;
    int tc = tid & 15;
    float acc[4][4] = {};
#pragma unroll
    for (int k = 0; k < 64; k++) {
        float4 w4 = ((const float4*)&Ws[k][0])[tc];
        float x0 = Xs[tr + 0][k], x1 = Xs[tr + 1][k];
        float x2 = Xs[tr + 2][k], x3 = Xs[tr + 3][k];
        acc[0][0] += x0 * w4.x; acc[0][1] += x0 * w4.y; acc[0][2] += x0 * w4.z; acc[0][3] += x0 * w4.w;
        acc[1][0] += x1 * w4.x; acc[1][1] += x1 * w4.y; acc[1][2] += x1 * w4.z; acc[1][3] += x1 * w4.w;
        acc[2][0] += x2 * w4.x; acc[2][1] += x2 * w4.y; acc[2][2] += x2 * w4.z; acc[2][3] += x2 * w4.w;
        acc[3][0] += x3 * w4.x; acc[3][1] += x3 * w4.y; acc[3][2] += x3 * w4.z; acc[3][3] += x3 * w4.w;
    }
#pragma unroll
    for (int i = 0; i < 4; i++) {
        int r = row0 + tr + i;
        if (r < n) {
            float dv = g_dinv[g][r];
            __half2 p0 = __floats2half2_rn(acc[i][0] * dv, acc[i][1] * dv);
            __half2 p1 = __floats2half2_rn(acc[i][2] * dv, acc[i][3] * dv);
            uint2 u = make_uint2(*(unsigned*)&p0, *(unsigned*)&p1);
            *(uint2*)&Y[(size_t)r * 64 + tc * 4] = u;
        }
    }
}

// ---------------- aggregation: Z = dinv[d]*(Σ h'[src] + h'[d]) + b ----------------
// one warp per node, lane owns 2 cols; coef-free adds; fused heads on layer 2

__global__ void agg_kernel(const float* __restrict__ b, int n,
                           const float* __restrict__ Wy, const float* __restrict__ by,
                           const float* __restrict__ Wp, const float* __restrict__ bp,
                           const float* __restrict__ Wb, const float* __restrict__ bb,
                           float* __restrict__ out) {
    int g = blockIdx.y;
    int warp = (blockIdx.x * blockDim.x + threadIdx.x) >> 5;
    int lane = threadIdx.x & 31;
    if (warp >= n) return;
    const __half2* __restrict__ h2 = (const __half2*)g_A[g];
    const int*     __restrict__ ep = g_esrc[g];

    float2 hv = __half22float2(h2[(size_t)warp * 32 + lane]);  // self (already dinv-scaled)
    float ax0 = hv.x, ay0 = hv.y;
    float ax1 = 0.f, ay1 = 0.f;

    int j = g_rowptr[g][warp];
    int end = g_rowptr[g][warp + 1];

    for (; j + 4 <= end; j += 4) {
        int s0 = ep[j], s1 = ep[j + 1], s2 = ep[j + 2], s3 = ep[j + 3];
        float2 v0 = __half22float2(h2[(size_t)s0 * 32 + lane]);
        float2 v1 = __half22float2(h2[(size_t)s1 * 32 + lane]);
        float2 v2 = __half22float2(h2[(size_t)s2 * 32 + lane]);
        float2 v3 = __half22float2(h2[(size_t)s3 * 32 + lane]);
        ax0 += v0.x; ay0 += v0.y;
        ax1 += v1.x; ay1 += v1.y;
        ax0 += v2.x; ay0 += v2.y;
        ax1 += v3.x; ay1 += v3.y;
    }
    for (; j < end; j++) {
        float2 v0 = __half22float2(h2[(size_t)ep[j] * 32 + lane]);
        ax0 += v0.x; ay0 += v0.y;
    }
    float dd = g_dinv[g][warp];
    float2 bv = *(const float2*)&b[lane * 2];
    float zx = fmaf(dd, ax0 + ax1, bv.x);
    float zy = fmaf(dd, ay0 + ay1, bv.y);

    if (!Wy) {  // layer 1: store Z1 (fp32)
        *(float2*)&g_B[g][(size_t)warp * 64 + lane * 2] = make_float2(zx, zy);
        return;
    }
    // layer 2: fused heads
    if (g == 0) {
        float2 wy = *(const float2*)&Wy[lane * 2];
        float2 wp = *(const float2*)&Wp[lane * 2];
        float2 wb = *(const float2*)&Wb[lane * 2];
        float sy = zx * wy.x + zy * wy.y;
        float sp = zx * wp.x + zy * wp.y;
        float sb = zx * wb.x + zy * wb.y;
#pragma unroll
        for (int o = 16; o; o >>= 1) {
            sy += __shfl_down_sync(0xFFFFFFFFu, sy, o);
            sp += __shfl_down_sync(0xFFFFFFFFu, sp, o);
            sb += __shfl_down_sync(0xFFFFFFFFu, sb, o);
        }
        if (lane == 0) {
            out[warp]                 = fmaxf(sy + by[0], 0.f);  // yi
            out[(size_t)n + warp]     = fmaxf(sp + bp[0], 0.f);  // fprob
            out[(size_t)3 * n + warp] = fmaxf(sb + bb[0], 0.f);  // treat_prob
        }
    } else {
        float2 wp = *(const float2*)&Wp[lane * 2];
        float sf = zx * wp.x + zy * wp.y;
#pragma unroll
        for (int o = 16; o; o >>= 1)
            sf += __shfl_down_sync(0xFFFFFFFFu, sf, o);
        if (lane == 0)
            out[(size_t)2 * n + warp] = fmaxf(sf + bp[0], 0.f);  // fprob_f
    }
}

// ---------------- launch ----------------

extern "C" void kernel_launch(void* const* d_in, const int* in_sizes, int n_in,
                              void* d_out, int out_size) {
    const float* x   = (const float*)d_in[0];
    const int*   ei  = (const int*)d_in[1];    // int32 on the wire (JAX x64 disabled)
    const float* fx  = (const float*)d_in[2];
    const int*   fei = (const int*)d_in[3];
    const float* W1 = (const float*)d_in[4];
    const float* b1 = (const float*)d_in[5];
    const float* W2 = (const float*)d_in[6];
    const float* b2 = (const float*)d_in[7];
    const float* Wy = (const float*)d_in[8];
    const float* by = (const float*)d_in[9];
    const float* Wp = (const float*)d_in[10];
    const float* bp = (const float*)d_in[11];
    const float* Wb = (const float*)d_in[12];
    const float* bb = (const float*)d_in[13];

    int n = in_sizes[0] / 64;
    int E = in_sizes[1] / 2;
    float* out = (float*)d_out;

    int nb_e = (E + 255) / 256;
    int nb_g = (n + 63) / 64;
    int nb_s = (n + 1023) / 1024;

    dim3 ge(nb_e, 2);
    dim3 gs(nb_s, 2);
    dim3 gn((n + 255) / 256, 2);
    dim3 gcg(nb_e + nb_g, 2);
    dim3 gg(nb_g, 2);
    dim3 gw((n * 32 + 255) / 256, 2);

    // zero degree arrays (both graphs, contiguous)
    void* deg_ptr;
    cudaGetSymbolAddress(&deg_ptr, g_deg);
    cudaMemsetAsync(deg_ptr, 0, sizeof(int) * 2 * N_CAP);

    // CSR build (shared by both layers)
    hist_kernel<<<ge, 256>>>(ei, fei, E, n);
    scan1_kernel<<<gs, 1024>>>(n);              // + dinv
    scan3_kernel<<<gn, 256>>>(n, E, nb_s);      // rowptr/cursor (scan2 folded in)

    // claim (CSR scatter) overlapped with layer-1 GEMM (h' = dinv * X@W1, fp16)
    claimgemm_kernel<<<gcg, 256>>>(ei, fei, x, fx, W1, E, n, nb_e);
    // Z1 = dinv*(gather + self) + b1
    agg_kernel<<<gw, 256>>>(b1, n, nullptr, nullptr, nullptr, nullptr, nullptr, nullptr, nullptr);

    // layer 2: h' = dinv * relu(Z1)@W2 ; Z2 + fused heads -> out
    gemm64_kernel<<<gg, 256>>>(W2, n);
    agg_kernel<<<gw, 256>>>(b2, n, Wy, by, Wp, bp, Wb, bb, out);
}